// round 17
// baseline (speedup 1.0000x reference)
#include <cuda_runtime.h>
#include <stdint.h>

#define N_NODES 50000
#define N_EDGES 800000
#define FEAT    128
#define NBLK    ((N_NODES + 255) / 256)

typedef unsigned long long u64;
typedef unsigned int uint;

// Scratch (static device globals; no allocation allowed)
__device__ float g_mean1[(size_t)N_NODES * FEAT];
__device__ float g_h[(size_t)N_NODES * FEAT];
__device__ float g_p[(size_t)N_NODES * 48];   // h @ Wl2, cols 40-47 zero
__device__ float g_q[(size_t)N_NODES * 40];   // h @ Wr2
__device__ int   g_deg[N_NODES];
__device__ int   g_row[N_NODES + 1];
__device__ int   g_cursor[N_NODES];
__device__ int   g_csr[N_EDGES];
__device__ int   g_idx_is32;

// ---------------------------------------------------------------------------
// Init: zero degree counters; thread 0 detects edge_index dtype (reference
// declares int64 but JAX x64-off emits int32).
// ---------------------------------------------------------------------------
__global__ void init_kernel(const long long* __restrict__ ei) {
    int i = blockIdx.x * blockDim.x + threadIdx.x;
    if (i < N_NODES) g_deg[i] = 0;
    if (i == 0) {
        int is32 = 0;
        for (int k = 0; k < 64; k++) {
            long long v = ei[k];
            if (v < 0 || v >= N_NODES) { is32 = 1; break; }
        }
        g_idx_is32 = is32;
    }
}

__device__ __forceinline__ int load_src(const void* ei, int e) {
    return g_idx_is32 ? __ldg(&((const int*)ei)[e])
                      : (int)__ldg(&((const long long*)ei)[e]);
}
__device__ __forceinline__ int load_dst(const void* ei, int e) {
    return g_idx_is32 ? __ldg(&((const int*)ei)[N_EDGES + e])
                      : (int)__ldg(&((const long long*)ei)[N_EDGES + e]);
}

// ---------------------------------------------------------------------------
// CSR build: histogram -> fused single-block scan -> fill
// ---------------------------------------------------------------------------
__global__ void hist_kernel(const void* __restrict__ ei) {
    int e = blockIdx.x * blockDim.x + threadIdx.x;
    if (e < N_EDGES) atomicAdd(&g_deg[load_dst(ei, e)], 1);
}

__global__ void __launch_bounds__(1024)
scan_fused_kernel() {
    __shared__ int sh[1024];
    const int t = threadIdx.x;
    const int c0 = t * 49;                       // 1024*49 = 50176 >= N
    const int c1 = min(c0 + 49, N_NODES);
    int lsum = 0;
    for (int i = c0; i < c1; i++) lsum += g_deg[i];
    sh[t] = lsum;
    __syncthreads();
    for (int o = 1; o < 1024; o <<= 1) {
        int add = (t >= o) ? sh[t - o] : 0;
        __syncthreads();
        sh[t] += add;
        __syncthreads();
    }
    int run = sh[t] - lsum;                      // exclusive prefix
    for (int i = c0; i < c1; i++) {
        g_row[i] = run;
        g_cursor[i] = run;
        run += g_deg[i];
    }
    if (t == 0) g_row[N_NODES] = N_EDGES;
}

__global__ void fill_kernel(const void* __restrict__ ei) {
    int e = blockIdx.x * blockDim.x + threadIdx.x;
    if (e < N_EDGES) {
        int d = load_dst(ei, e);
        int pos = atomicAdd(&g_cursor[d], 1);
        g_csr[pos] = load_src(ei, e);
    }
}

// ---------------------------------------------------------------------------
// CSR mean-aggregation over 128-feat rows (layer 1): one warp per dst node.
// ---------------------------------------------------------------------------
__global__ void __launch_bounds__(256)
aggregate_kernel(const float* __restrict__ feat, float* __restrict__ outm) {
    int w    = (blockIdx.x * blockDim.x + threadIdx.x) >> 5;
    int lane = threadIdx.x & 31;
    if (w >= N_NODES) return;

    int start = __ldg(&g_row[w]);
    int end   = __ldg(&g_row[w + 1]);

    float4 acc = make_float4(0.f, 0.f, 0.f, 0.f);
    int i = start;
    for (; i + 4 <= end; i += 4) {
        int s0 = __ldg(&g_csr[i]);
        int s1 = __ldg(&g_csr[i + 1]);
        int s2 = __ldg(&g_csr[i + 2]);
        int s3 = __ldg(&g_csr[i + 3]);
        float4 v0 = __ldg((const float4*)(feat + (size_t)s0 * FEAT) + lane);
        float4 v1 = __ldg((const float4*)(feat + (size_t)s1 * FEAT) + lane);
        float4 v2 = __ldg((const float4*)(feat + (size_t)s2 * FEAT) + lane);
        float4 v3 = __ldg((const float4*)(feat + (size_t)s3 * FEAT) + lane);
        acc.x += (v0.x + v1.x) + (v2.x + v3.x);
        acc.y += (v0.y + v1.y) + (v2.y + v3.y);
        acc.z += (v0.z + v1.z) + (v2.z + v3.z);
        acc.w += (v0.w + v1.w) + (v2.w + v3.w);
    }
    for (; i < end; i++) {
        int s = __ldg(&g_csr[i]);
        float4 v = __ldg((const float4*)(feat + (size_t)s * FEAT) + lane);
        acc.x += v.x; acc.y += v.y; acc.z += v.z; acc.w += v.w;
    }
    float inv = 1.0f / fmaxf((float)(end - start), 1.0f);
    acc.x *= inv; acc.y *= inv; acc.z *= inv; acc.w *= inv;
    ((float4*)(outm + (size_t)w * FEAT))[lane] = acc;
}

// ---------------------------------------------------------------------------
// Layer-1 GEMM via TF32 mma.sync m16n8k8 (identical to R16 passing version):
//   U[n] = [mean[n], x[n]] (K=256), W = [Wl1; Wr1], h = relu(U W + b1)
// ---------------------------------------------------------------------------
template <int TM, int JP, int JREAL, bool RELU>
__global__ void __launch_bounds__(256, 1)
layer_mma(const float* __restrict__ mean, const float* __restrict__ xroot,
          const float* __restrict__ Wl, const float* __restrict__ Wr,
          const float* __restrict__ bias, float* __restrict__ out) {
    constexpr int K    = 256;
    constexpr int KK   = K / 8;
    constexpr int WM   = TM / 32;
    constexpr int WN   = 8 / WM;
    constexpr int NJT  = JP / 8;
    constexpr int NT_W = NJT / WN;
    constexpr int SUS  = K + 4;        // 260 (mod 32 == 4) -> conflict-free A frags
    static_assert(NT_W == 4, "");

    extern __shared__ uint sm[];
    uint*  sB = sm;                         // KK*NJT*64 (fragment order)
    uint*  sU = sB + KK * NJT * 64;         // TM*SUS
    float* sb = (float*)(sU + TM * SUS);    // JP

    const int t = threadIdx.x;

    for (int idx = t; idx < KK * NJT * 32; idx += 256) {
        int lane = idx & 31, rem = idx >> 5;
        int jt = rem % NJT, kk = rem / NJT;
        int krow = kk * 8 + (lane & 3);
        int j    = jt * 8 + (lane >> 2);
        float w0 = 0.f, w1 = 0.f;
        if (j < JREAL) {
            w0 = (krow < 128) ? __ldg(&Wl[krow * JREAL + j])
                              : __ldg(&Wr[(krow - 128) * JREAL + j]);
            int k2 = krow + 4;
            w1 = (k2 < 128) ? __ldg(&Wl[k2 * JREAL + j])
                            : __ldg(&Wr[(k2 - 128) * JREAL + j]);
        }
        uint u0, u1;
        asm("cvt.rna.tf32.f32 %0, %1;" : "=r"(u0) : "f"(w0));
        asm("cvt.rna.tf32.f32 %0, %1;" : "=r"(u1) : "f"(w1));
        sB[((kk * NJT + jt) * 32 + lane) * 2 + 0] = u0;
        sB[((kk * NJT + jt) * 32 + lane) * 2 + 1] = u1;
    }
    for (int idx = t; idx < JP; idx += 256)
        sb[idx] = (idx < JREAL) ? __ldg(&bias[idx]) : 0.f;

    const int wid = t >> 5, lane = t & 31;
    const int wm = wid % WM, wn = wid / WM;
    const int g = lane >> 2, t4 = lane & 3;
    const int ntiles = (N_NODES + TM - 1) / TM;

    for (int tile = blockIdx.x; tile < ntiles; tile += gridDim.x) {
        const int base = tile * TM;
        __syncthreads();

        for (int idx = t; idx < TM * (K / 4); idx += 256) {
            int k4 = idx & 63, m = idx >> 6;
            int node = min(base + m, N_NODES - 1);
            float4 v = (k4 < 32)
                ? __ldg((const float4*)(mean  + (size_t)node * FEAT) + k4)
                : __ldg((const float4*)(xroot + (size_t)node * FEAT) + (k4 - 32));
            uint4 u;
            asm("cvt.rna.tf32.f32 %0, %1;" : "=r"(u.x) : "f"(v.x));
            asm("cvt.rna.tf32.f32 %0, %1;" : "=r"(u.y) : "f"(v.y));
            asm("cvt.rna.tf32.f32 %0, %1;" : "=r"(u.z) : "f"(v.z));
            asm("cvt.rna.tf32.f32 %0, %1;" : "=r"(u.w) : "f"(v.w));
            *(uint4*)(sU + m * SUS + k4 * 4) = u;
        }
        __syncthreads();

        float acc[2][NT_W][4];
#pragma unroll
        for (int mt = 0; mt < 2; mt++)
#pragma unroll
            for (int nt = 0; nt < NT_W; nt++)
#pragma unroll
                for (int q = 0; q < 4; q++) acc[mt][nt][q] = 0.f;

#pragma unroll 4
        for (int kk = 0; kk < KK; kk++) {
            uint a[2][4];
#pragma unroll
            for (int mt = 0; mt < 2; mt++) {
                const uint* p = sU + (wm * 32 + mt * 16 + g) * SUS + kk * 8 + t4;
                a[mt][0] = p[0];
                a[mt][1] = p[8 * SUS];
                a[mt][2] = p[4];
                a[mt][3] = p[8 * SUS + 4];
            }
#pragma unroll
            for (int nt = 0; nt < NT_W; nt++) {
                int jt = wn * NT_W + nt;
                uint2 b = *(const uint2*)(sB + ((kk * NJT + jt) * 32 + lane) * 2);
#pragma unroll
                for (int mt = 0; mt < 2; mt++) {
                    asm("mma.sync.aligned.m16n8k8.row.col.f32.tf32.tf32.f32 "
                        "{%0,%1,%2,%3}, {%4,%5,%6,%7}, {%8,%9}, {%0,%1,%2,%3};"
                        : "+f"(acc[mt][nt][0]), "+f"(acc[mt][nt][1]),
                          "+f"(acc[mt][nt][2]), "+f"(acc[mt][nt][3])
                        : "r"(a[mt][0]), "r"(a[mt][1]), "r"(a[mt][2]), "r"(a[mt][3]),
                          "r"(b.x), "r"(b.y));
                }
            }
        }

#pragma unroll
        for (int mt = 0; mt < 2; mt++) {
            int r0 = base + wm * 32 + mt * 16 + g;
            int r1 = r0 + 8;
#pragma unroll
            for (int nt = 0; nt < NT_W; nt++) {
                int j0 = (wn * NT_W + nt) * 8 + 2 * t4;
                if (j0 >= JREAL) continue;
                float bz0 = sb[j0], bz1 = sb[j0 + 1];
                float c0 = acc[mt][nt][0] + bz0, c1 = acc[mt][nt][1] + bz1;
                float c2 = acc[mt][nt][2] + bz0, c3 = acc[mt][nt][3] + bz1;
                if (RELU) {
                    c0 = fmaxf(c0, 0.f); c1 = fmaxf(c1, 0.f);
                    c2 = fmaxf(c2, 0.f); c3 = fmaxf(c3, 0.f);
                }
                if (r0 < N_NODES)
                    *(float2*)(out + (size_t)r0 * JREAL + j0) = make_float2(c0, c1);
                if (r1 < N_NODES)
                    *(float2*)(out + (size_t)r1 * JREAL + j0) = make_float2(c2, c3);
            }
        }
    }
}

// ---------------------------------------------------------------------------
// Layer-2 projection GEMM (K=128): p = h @ Wl2 (cols 0-39, pad 48 with zeros),
// q = h @ Wr2 (cols 48-87 -> g_q 40-wide). No bias/act here.
// TM=128: WM=4, WN=2. JP=96 cols: NJT=12, NT_W=6.
// ---------------------------------------------------------------------------
__global__ void __launch_bounds__(256, 1)
proj2_mma(const float* __restrict__ h,
          const float* __restrict__ Wl, const float* __restrict__ Wr,
          float* __restrict__ pbuf, float* __restrict__ qbuf) {
    constexpr int TM = 128, JP = 96, JR = 40;
    constexpr int K = 128, KK = K / 8;      // 16
    constexpr int WM = 4, WN = 2;
    constexpr int NJT = JP / 8;             // 12
    constexpr int NT_W = NJT / WN;          // 6
    constexpr int SUS = K + 4;              // 132 (mod 32 == 4)

    extern __shared__ uint sm[];
    uint* sB = sm;                          // KK*NJT*64 = 12288
    uint* sU = sB + KK * NJT * 64;          // TM*SUS = 16896

    const int t = threadIdx.x;

    // Stage B fragments: col j<40 -> Wl2, 48<=j<88 -> Wr2, else 0
    for (int idx = t; idx < KK * NJT * 32; idx += 256) {
        int lane = idx & 31, rem = idx >> 5;
        int jt = rem % NJT, kk = rem / NJT;
        int k0 = kk * 8 + (lane & 3);
        int j  = jt * 8 + (lane >> 2);
        float w0 = 0.f, w1 = 0.f;
        if (j < JR) {
            w0 = __ldg(&Wl[k0 * JR + j]);
            w1 = __ldg(&Wl[(k0 + 4) * JR + j]);
        } else if (j >= 48 && j < 48 + JR) {
            w0 = __ldg(&Wr[k0 * JR + (j - 48)]);
            w1 = __ldg(&Wr[(k0 + 4) * JR + (j - 48)]);
        }
        uint u0, u1;
        asm("cvt.rna.tf32.f32 %0, %1;" : "=r"(u0) : "f"(w0));
        asm("cvt.rna.tf32.f32 %0, %1;" : "=r"(u1) : "f"(w1));
        sB[((kk * NJT + jt) * 32 + lane) * 2 + 0] = u0;
        sB[((kk * NJT + jt) * 32 + lane) * 2 + 1] = u1;
    }

    const int wid = t >> 5, lane = t & 31;
    const int wm = wid % WM, wn = wid / WM;
    const int g = lane >> 2, t4 = lane & 3;
    const int ntiles = (N_NODES + TM - 1) / TM;

    for (int tile = blockIdx.x; tile < ntiles; tile += gridDim.x) {
        const int base = tile * TM;
        __syncthreads();

        for (int idx = t; idx < TM * (K / 4); idx += 256) {
            int k4 = idx & 31, m = idx >> 5;
            int node = min(base + m, N_NODES - 1);
            float4 v = __ldg((const float4*)(h + (size_t)node * FEAT) + k4);
            uint4 u;
            asm("cvt.rna.tf32.f32 %0, %1;" : "=r"(u.x) : "f"(v.x));
            asm("cvt.rna.tf32.f32 %0, %1;" : "=r"(u.y) : "f"(v.y));
            asm("cvt.rna.tf32.f32 %0, %1;" : "=r"(u.z) : "f"(v.z));
            asm("cvt.rna.tf32.f32 %0, %1;" : "=r"(u.w) : "f"(v.w));
            *(uint4*)(sU + m * SUS + k4 * 4) = u;
        }
        __syncthreads();

        float acc[2][NT_W][4];
#pragma unroll
        for (int mt = 0; mt < 2; mt++)
#pragma unroll
            for (int nt = 0; nt < NT_W; nt++)
#pragma unroll
                for (int q = 0; q < 4; q++) acc[mt][nt][q] = 0.f;

#pragma unroll 4
        for (int kk = 0; kk < KK; kk++) {
            uint a[2][4];
#pragma unroll
            for (int mt = 0; mt < 2; mt++) {
                const uint* p = sU + (wm * 32 + mt * 16 + g) * SUS + kk * 8 + t4;
                a[mt][0] = p[0];
                a[mt][1] = p[8 * SUS];
                a[mt][2] = p[4];
                a[mt][3] = p[8 * SUS + 4];
            }
#pragma unroll
            for (int nt = 0; nt < NT_W; nt++) {
                int jt = wn * NT_W + nt;
                uint2 b = *(const uint2*)(sB + ((kk * NJT + jt) * 32 + lane) * 2);
#pragma unroll
                for (int mt = 0; mt < 2; mt++) {
                    asm("mma.sync.aligned.m16n8k8.row.col.f32.tf32.tf32.f32 "
                        "{%0,%1,%2,%3}, {%4,%5,%6,%7}, {%8,%9}, {%0,%1,%2,%3};"
                        : "+f"(acc[mt][nt][0]), "+f"(acc[mt][nt][1]),
                          "+f"(acc[mt][nt][2]), "+f"(acc[mt][nt][3])
                        : "r"(a[mt][0]), "r"(a[mt][1]), "r"(a[mt][2]), "r"(a[mt][3]),
                          "r"(b.x), "r"(b.y));
                }
            }
        }

#pragma unroll
        for (int mt = 0; mt < 2; mt++) {
            int r0 = base + wm * 32 + mt * 16 + g;
            int r1 = r0 + 8;
#pragma unroll
            for (int nt = 0; nt < NT_W; nt++) {
                int j0 = (wn * NT_W + nt) * 8 + 2 * t4;
                float c0 = acc[mt][nt][0], c1 = acc[mt][nt][1];
                float c2 = acc[mt][nt][2], c3 = acc[mt][nt][3];
                if (j0 < 48) {              // p part (cols 40-47 are zeros)
                    if (r0 < N_NODES)
                        *(float2*)(pbuf + (size_t)r0 * 48 + j0) = make_float2(c0, c1);
                    if (r1 < N_NODES)
                        *(float2*)(pbuf + (size_t)r1 * 48 + j0) = make_float2(c2, c3);
                } else {
                    int jq = j0 - 48;
                    if (jq < JR) {          // q part
                        if (r0 < N_NODES)
                            *(float2*)(qbuf + (size_t)r0 * JR + jq) = make_float2(c0, c1);
                        if (r1 < N_NODES)
                            *(float2*)(qbuf + (size_t)r1 * JR + jq) = make_float2(c2, c3);
                    }
                }
            }
        }
    }
}

// ---------------------------------------------------------------------------
// Final: out[n] = mean_agg(p)[n][0:40] + q[n] + b2. One warp per dst node;
// 2 edges per iteration (half-warp each, 12 quads of the 48-col p rows).
// ---------------------------------------------------------------------------
__global__ void __launch_bounds__(256)
agg2_combine_kernel(const float* __restrict__ p, const float* __restrict__ q,
                    const float* __restrict__ b2, float* __restrict__ out) {
    int w    = (blockIdx.x * blockDim.x + threadIdx.x) >> 5;
    int lane = threadIdx.x & 31;
    if (w >= N_NODES) return;

    int start = __ldg(&g_row[w]);
    int end   = __ldg(&g_row[w + 1]);

    int half = lane >> 4;          // which edge of the pair
    int qd   = lane & 15;          // quad within the 48-col row
    bool act = qd < 12;

    float4 acc = make_float4(0.f, 0.f, 0.f, 0.f);
    for (int i = start; i < end; i += 2) {
        int e = i + half;
        if (act && e < end) {
            int s = __ldg(&g_csr[e]);
            float4 v = __ldg((const float4*)(p + (size_t)s * 48) + qd);
            acc.x += v.x; acc.y += v.y; acc.z += v.z; acc.w += v.w;
        }
    }
    acc.x += __shfl_down_sync(0xffffffff, acc.x, 16);
    acc.y += __shfl_down_sync(0xffffffff, acc.y, 16);
    acc.z += __shfl_down_sync(0xffffffff, acc.z, 16);
    acc.w += __shfl_down_sync(0xffffffff, acc.w, 16);

    if (lane < 10) {               // 40 real cols = 10 quads
        float inv = 1.0f / fmaxf((float)(end - start), 1.0f);
        float4 qv = __ldg((const float4*)(q + (size_t)w * 40) + lane);
        float4 bv = __ldg((const float4*)b2 + lane);
        float4 r;
        r.x = acc.x * inv + qv.x + bv.x;
        r.y = acc.y * inv + qv.y + bv.y;
        r.z = acc.z * inv + qv.z + bv.z;
        r.w = acc.w * inv + qv.w + bv.w;
        *((float4*)(out + (size_t)w * 40) + lane) = r;
    }
}

// ---------------------------------------------------------------------------
extern "C" void kernel_launch(void* const* d_in, const int* in_sizes, int n_in,
                              void* d_out, int out_size) {
    const float* x   = (const float*)d_in[0];
    const void*  ei  = d_in[1];
    const float* Wl1 = (const float*)d_in[2];
    const float* Wr1 = (const float*)d_in[3];
    const float* b1  = (const float*)d_in[4];
    const float* Wl2 = (const float*)d_in[5];
    const float* Wr2 = (const float*)d_in[6];
    const float* b2  = (const float*)d_in[7];
    float*       out = (float*)d_out;

    float *mean1, *hbuf, *pbuf, *qbuf;
    cudaGetSymbolAddress((void**)&mean1, g_mean1);
    cudaGetSymbolAddress((void**)&hbuf,  g_h);
    cudaGetSymbolAddress((void**)&pbuf,  g_p);
    cudaGetSymbolAddress((void**)&qbuf,  g_q);

    const int SMEM1 = (32 * 16 * 64 + 64 * 260 + 128) * 4;   // layer1
    const int SMEMP = (16 * 12 * 64 + 128 * 132) * 4;        // proj2
    cudaFuncSetAttribute(layer_mma<64, 128, 128, true>,
                         cudaFuncAttributeMaxDynamicSharedMemorySize, SMEM1);
    cudaFuncSetAttribute(proj2_mma,
                         cudaFuncAttributeMaxDynamicSharedMemorySize, SMEMP);

    const int EB = (N_EDGES + 255) / 256;
    const int AGG_BLOCKS = (N_NODES * 32 + 255) / 256;

    // CSR build (per replay — deterministic)
    init_kernel<<<NBLK, 256>>>((const long long*)ei);
    hist_kernel<<<EB, 256>>>(ei);
    scan_fused_kernel<<<1, 1024>>>();
    fill_kernel<<<EB, 256>>>(ei);

    // Layer 1: aggregate 128-feat, then fused GEMM
    aggregate_kernel<<<AGG_BLOCKS, 256>>>(x, mean1);
    layer_mma<64, 128, 128, true><<<152, 256, SMEM1>>>(mean1, x, Wl1, Wr1, b1, hbuf);

    // Layer 2: project first (40+40 cols), then aggregate the 48-col rows
    proj2_mma<<<152, 256, SMEMP>>>(hbuf, Wl2, Wr2, pbuf, qbuf);
    agg2_combine_kernel<<<AGG_BLOCKS, 256>>>(pbuf, qbuf, b2, out);
}